// round 2
// baseline (speedup 1.0000x reference)
#include <cuda_runtime.h>
#include <cstdint>

#define B_ROWS 65536
#define D_IN   784
#define DIMZ   128
#define NCLS   10
#define KPROP  64

__device__ float g_h[B_ROWS * DIMZ];
__device__ float g_kappa[B_ROWS];
__device__ float g_w[B_ROWS];

// exact-rounding helpers (prevent FMA contraction; XLA emits separate mul/add)
__device__ __forceinline__ float MULR(float a, float b) { return __fmul_rn(a, b); }
__device__ __forceinline__ float ADDR(float a, float b) { return __fadd_rn(a, b); }
__device__ __forceinline__ float SUBR(float a, float b) { return __fsub_rn(a, b); }
__device__ __forceinline__ float DIVR(float a, float b) { return __fdiv_rn(a, b); }

// ---------------- JAX Threefry-2x32 (20 rounds), partitionable mode ----------------
struct K2 { uint32_t a, b; };

__device__ __forceinline__ void tf2x32(uint32_t k0, uint32_t k1, uint32_t c0, uint32_t c1,
                                       uint32_t &o0, uint32_t &o1) {
    uint32_t ks2 = k0 ^ k1 ^ 0x1BD11BDAu;
    uint32_t x0 = c0 + k0;
    uint32_t x1 = c1 + k1;
#define TFR(r) { x0 += x1; x1 = __funnelshift_l(x1, x1, (r)); x1 ^= x0; }
    TFR(13) TFR(15) TFR(26) TFR(6)
    x0 += k1;  x1 += ks2 + 1u;
    TFR(17) TFR(29) TFR(16) TFR(24)
    x0 += ks2; x1 += k0 + 2u;
    TFR(13) TFR(15) TFR(26) TFR(6)
    x0 += k0;  x1 += k1 + 3u;
    TFR(17) TFR(29) TFR(16) TFR(24)
    x0 += k1;  x1 += ks2 + 4u;
    TFR(13) TFR(15) TFR(26) TFR(6)
    x0 += ks2; x1 += k0 + 5u;
#undef TFR
    o0 = x0; o1 = x1;
}

__device__ __forceinline__ K2 keyderive(K2 k, uint32_t hi, uint32_t lo) {
    K2 r; tf2x32(k.a, k.b, hi, lo, r.a, r.b); return r;
}
__device__ __forceinline__ uint32_t bits32(K2 k, uint32_t hi, uint32_t lo) {
    uint32_t a, b; tf2x32(k.a, k.b, hi, lo, a, b); return a ^ b;
}
__device__ __forceinline__ float u01_from_bits(uint32_t bits) {
    return SUBR(__uint_as_float((bits >> 9) | 0x3f800000u), 1.0f);   // [0,1)
}
__device__ __forceinline__ float uniform01(K2 k) { return u01_from_bits(bits32(k, 0u, 0u)); }

// XLA ErfInv f32 (Giles), un-contracted
__device__ __forceinline__ float erfinv_xla(float x) {
    float w = -log1pf(-MULR(x, x));
    float p;
    if (w < 5.0f) {
        w = SUBR(w, 2.5f);
        p = 2.81022636e-08f;
        p = ADDR(MULR(p, w), 3.43273939e-07f);
        p = ADDR(MULR(p, w), -3.5233877e-06f);
        p = ADDR(MULR(p, w), -4.39150654e-06f);
        p = ADDR(MULR(p, w), 0.00021858087f);
        p = ADDR(MULR(p, w), -0.00125372503f);
        p = ADDR(MULR(p, w), -0.00417768164f);
        p = ADDR(MULR(p, w), 0.246640727f);
        p = ADDR(MULR(p, w), 1.50140941f);
    } else {
        w = SUBR(sqrtf(w), 3.0f);
        p = -0.000200214257f;
        p = ADDR(MULR(p, w), 0.000100950558f);
        p = ADDR(MULR(p, w), 0.00134934322f);
        p = ADDR(MULR(p, w), -0.00367342844f);
        p = ADDR(MULR(p, w), 0.00573950773f);
        p = ADDR(MULR(p, w), -0.0076224613f);
        p = ADDR(MULR(p, w), 0.00943887047f);
        p = ADDR(MULR(p, w), 1.00167406f);
        p = ADDR(MULR(p, w), 2.83297682f);
    }
    return MULR(p, x);
}

// jax.random.normal: uniform over [nextafter(-1,0), 1), then sqrt(2)*erfinv
__device__ __forceinline__ float normal_from_bits(uint32_t bits) {
    const float LO = -0.99999994f;
    float f = u01_from_bits(bits);
    float val = fmaxf(LO, ADDR(MULR(f, 2.0f), LO));   // (hi-lo) rounds to exactly 2.0f
    return MULR(1.41421356237309515f, erfinv_xla(val));
}
__device__ __forceinline__ float normal_scalar(K2 k) { return normal_from_bits(bits32(k, 0u, 0u)); }

// jax._src.random._gamma_one, log_space=True, alpha=63.5 (boost path dead but split consumed)
__device__ float loggamma_a635(K2 key_elem) {
    const float d = SUBR(63.5f, 0.33333334f);
    const float c = DIVR(0.33333334f, sqrtf(d));
    K2 key = keyderive(key_elem, 0u, 0u);      // key, subkey = split(key); subkey (boost) unused
    float V = 1.0f;
    for (int it = 0; it < 64; ++it) {
        K2 nkey = keyderive(key, 0u, 0u);      // key, x_key, U_key = split(key, 3)
        K2 xkey = keyderive(key, 0u, 1u);
        K2 Ukey = keyderive(key, 0u, 2u);
        key = nkey;
        float x = 0.0f, v = -1.0f;
        for (int j = 0; j < 8; ++j) {          // while v <= 0 (in practice 1 iteration)
            K2 sub = keyderive(xkey, 0u, 1u);
            x = normal_scalar(sub);
            v = ADDR(1.0f, MULR(x, c));
            if (v > 0.0f) break;
            xkey = keyderive(xkey, 0u, 0u);
        }
        float X = MULR(x, x);
        V = MULR(MULR(v, v), v);
        float U = uniform01(Ukey);
        if (U < SUBR(1.0f, MULR(0.0331f, MULR(X, X)))) break;                       // squeeze accept
        if (logf(U) < ADDR(MULR(X, 0.5f), MULR(d, ADDR(SUBR(1.0f, V), logf(V))))) break;
    }
    return ADDR(logf(d), logf(V));
}

__device__ __forceinline__ float beta_e(K2 kA, K2 kB) {
    float la = loggamma_a635(kA);
    float lb = loggamma_a635(kB);
    float mx = fmaxf(la, lb);
    float ea = expf(SUBR(la, mx));
    float eb = expf(SUBR(lb, mx));
    return DIVR(ea, ADDR(ea, eb));
}

// ---------------- kernel 1: h = x @ W_enc + b_enc ----------------
__global__ __launch_bounds__(256) void sgemm_kernel(const float* __restrict__ X,
                                                    const float* __restrict__ W,
                                                    const float* __restrict__ bias) {
    __shared__ float As[8][128];
    __shared__ float Bs[8][128];
    int tid = threadIdx.x;
    int tx  = tid & 15;
    int ty  = tid >> 4;
    int rowBase = blockIdx.x * 128;

    float acc[8][8];
#pragma unroll
    for (int i = 0; i < 8; i++)
#pragma unroll
        for (int j = 0; j < 8; j++) acc[i][j] = 0.0f;

    for (int k0 = 0; k0 < D_IN; k0 += 8) {
#pragma unroll
        for (int l = 0; l < 4; l++) {
            int idx = tid + l * 256;
            int r = idx >> 3, kk = idx & 7;
            As[kk][r] = X[(rowBase + r) * D_IN + k0 + kk];
        }
#pragma unroll
        for (int l = 0; l < 4; l++) {
            int idx = tid + l * 256;
            int kk = idx >> 7, cc = idx & 127;
            Bs[kk][cc] = W[(k0 + kk) * DIMZ + cc];
        }
        __syncthreads();
#pragma unroll
        for (int kk = 0; kk < 8; kk++) {
            float4 a0 = *(const float4*)&As[kk][ty * 8];
            float4 a1 = *(const float4*)&As[kk][ty * 8 + 4];
            float4 b0 = *(const float4*)&Bs[kk][tx * 8];
            float4 b1 = *(const float4*)&Bs[kk][tx * 8 + 4];
            float a[8] = {a0.x, a0.y, a0.z, a0.w, a1.x, a1.y, a1.z, a1.w};
            float b[8] = {b0.x, b0.y, b0.z, b0.w, b1.x, b1.y, b1.z, b1.w};
#pragma unroll
            for (int i = 0; i < 8; i++)
#pragma unroll
                for (int j = 0; j < 8; j++) acc[i][j] = fmaf(a[i], b[j], acc[i][j]);
        }
        __syncthreads();
    }
#pragma unroll
    for (int i = 0; i < 8; i++)
#pragma unroll
        for (int j = 0; j < 8; j++)
            g_h[(rowBase + ty * 8 + i) * DIMZ + tx * 8 + j] = acc[i][j] + bias[tx * 8 + j];
}

// ---------------- 128-thread block reduce ----------------
__device__ __forceinline__ float blockReduceSum128(float v, float* red) {
#pragma unroll
    for (int o = 16; o > 0; o >>= 1) v += __shfl_down_sync(0xffffffffu, v, o);
    if ((threadIdx.x & 31) == 0) red[threadIdx.x >> 5] = v;
    __syncthreads();
    float t = red[0] + red[1] + red[2] + red[3];
    __syncthreads();
    return t;
}

// ---------------- kernel 2: kappa = softplus(h @ W_var + b_var) + 1 ----------------
__global__ __launch_bounds__(128) void kappa_kernel(const float* __restrict__ Wvar,
                                                    const float* __restrict__ bvar) {
    int row = blockIdx.x;
    int j = threadIdx.x;
    __shared__ float red[4];
    float hv = g_h[row * DIMZ + j];
    float tot = blockReduceSum128(hv * Wvar[j], red);
    if (j == 0) {
        float xv = tot + bvar[0];
        float sp = fmaxf(xv, 0.0f) + log1pf(expf(-fabsf(xv)));
        g_kappa[row] = sp + 1.0f;
    }
}

// ---------------- kernel 3: lazy vMF rejection sampler (thread per row) ----------------
__global__ __launch_bounds__(256) void sampler_kernel() {
    int row = blockIdx.x * blockDim.x + threadIdx.x;
    if (row >= B_ROWS) return;

    K2 root; root.a = 0u; root.b = 42u;        // jax.random.key(42)
    K2 ke   = keyderive(root, 0u, 0u);         // ke, ku, kv = split(key, 3)
    K2 ku   = keyderive(root, 0u, 1u);
    K2 keyA = keyderive(ke, 0u, 0u);           // beta: key_a, key_b = split(ke)
    K2 keyB = keyderive(ke, 0u, 1u);

    float kap = g_kappa[row];
    float c  = sqrtf(ADDR(MULR(4.0f, MULR(kap, kap)), 16129.0f));
    float bt = DIVR(ADDR(MULR(-2.0f, kap), c), 127.0f);
    float ba = DIVR(127.0f, MULR(4.0f, kap));
    float s  = fminf(fmaxf(SUBR(kap, 10.0f), 0.0f), 1.0f);
    float bb = ADDR(MULR(ba, s), MULR(bt, SUBR(1.0f, s)));
    float aa = DIVR(ADDR(ADDR(127.0f, MULR(2.0f, kap)), c), 4.0f);
    float dd = SUBR(DIVR(MULR(MULR(4.0f, aa), bb), ADDR(1.0f, bb)),
                    MULR(127.0f, (float)4.844187086458591));

    float wsel = 0.0f;
    for (uint32_t k = 0; k < KPROP; k++) {
        uint32_t i = (uint32_t)row * 64u + k;
        float e = beta_e(keyderive(keyA, 0u, i), keyderive(keyB, 0u, i));
        float denom = SUBR(1.0f, MULR(SUBR(1.0f, bb), e));
        wsel = DIVR(SUBR(1.0f, MULR(ADDR(1.0f, bb), e)), denom);
        float t = DIVR(MULR(MULR(2.0f, aa), bb), denom);
        // u in [1e-20, 1-1e-20): f*(max-min)+min with (max-min)->1.0f
        float uf = fmaxf(1e-20f, ADDR(u01_from_bits(bits32(ku, 0u, i)), 1e-20f));
        float lhs = ADDR(SUBR(MULR(127.0f, logf(t)), t), dd);
        if (lhs > logf(uf)) break;
    }
    g_w[row] = wsel;
}

// ---------------- kernel 4: tangent normals + Householder + decoder ----------------
__global__ __launch_bounds__(128) void finish_kernel(const float* __restrict__ Wdec,
                                                     const float* __restrict__ bdec,
                                                     float* __restrict__ out) {
    int row = blockIdx.x;
    int j = threadIdx.x;
    __shared__ float red[4];
    __shared__ float zsh[DIMZ];

    float h = g_h[row * DIMZ + j];
    float s2 = blockReduceSum128(h * h, red);
    float mu = h / (sqrtf(s2) + 1e-8f);

    K2 root; root.a = 0u; root.b = 42u;
    K2 kv = keyderive(root, 0u, 2u);
    float vj = 0.0f;
    if (j >= 1) vj = normal_from_bits(bits32(kv, 0u, (uint32_t)row * 127u + (uint32_t)(j - 1)));
    float vs = blockReduceSum128(vj * vj, red);

    float w = g_w[row];
    float wperp = sqrtf(fmaxf(1.0f - w * w, 1e-10f));
    float x = (j == 0) ? w : wperp * (vj / sqrtf(vs));

    float uh = ((j == 0) ? 1.0f : 0.0f) - mu;
    float un = blockReduceSum128(uh * uh, red);
    uh = uh / (sqrtf(un) + 1e-5f);
    float xd = blockReduceSum128(x * uh, red);
    float z = x - 2.0f * xd * uh;

    zsh[j] = z;
    __syncthreads();
    if (j < NCLS) {
        float acc = bdec[j];
#pragma unroll 16
        for (int r = 0; r < DIMZ; r++) acc += zsh[r] * Wdec[r * NCLS + j];
        out[row * NCLS + j] = acc;
    }
}

extern "C" void kernel_launch(void* const* d_in, const int* in_sizes, int n_in,
                              void* d_out, int out_size) {
    const float* x    = (const float*)d_in[0];
    const float* Wenc = (const float*)d_in[1];
    const float* benc = (const float*)d_in[2];
    const float* Wvar = (const float*)d_in[3];
    const float* bvar = (const float*)d_in[4];
    const float* Wdec = (const float*)d_in[5];
    const float* bdec = (const float*)d_in[6];
    float* out = (float*)d_out;

    sgemm_kernel<<<B_ROWS / 128, 256>>>(x, Wenc, benc);
    kappa_kernel<<<B_ROWS, 128>>>(Wvar, bvar);
    sampler_kernel<<<B_ROWS / 256, 256>>>();
    finish_kernel<<<B_ROWS, 128>>>(Wdec, bdec, out);
}

// round 3
// speedup vs baseline: 1.3946x; 1.3946x over previous
#include <cuda_runtime.h>
#include <cstdint>

#define B_ROWS 65536
#define D_IN   784
#define DIMZ   128
#define NCLS   10
#define KPROP  64

__device__ float g_h[B_ROWS * DIMZ];     // stores mu (normalized h) after enc_kernel
__device__ float g_kappa[B_ROWS];
__device__ float g_w[B_ROWS];

// exact-rounding helpers (prevent FMA contraction; XLA emits separate mul/add)
__device__ __forceinline__ float MULR(float a, float b) { return __fmul_rn(a, b); }
__device__ __forceinline__ float ADDR(float a, float b) { return __fadd_rn(a, b); }
__device__ __forceinline__ float SUBR(float a, float b) { return __fsub_rn(a, b); }
__device__ __forceinline__ float DIVR(float a, float b) { return __fdiv_rn(a, b); }

// ---------------- packed f32x2 helpers ----------------
__device__ __forceinline__ void fma2(unsigned long long &d, unsigned long long a, unsigned long long b) {
    asm("fma.rn.f32x2 %0, %1, %2, %3;" : "=l"(d) : "l"(a), "l"(b), "l"(d));
}
__device__ __forceinline__ unsigned long long packf2(float lo, float hi) {
    unsigned long long r; asm("mov.b64 %0, {%1,%2};" : "=l"(r) : "f"(lo), "f"(hi)); return r;
}
__device__ __forceinline__ void unpackf2(unsigned long long v, float &lo, float &hi) {
    asm("mov.b64 {%0,%1}, %2;" : "=f"(lo), "=f"(hi) : "l"(v));
}

// ---------------- JAX Threefry-2x32 (20 rounds), partitionable mode ----------------
struct K2 { uint32_t a, b; };

__device__ __forceinline__ void tf2x32(uint32_t k0, uint32_t k1, uint32_t c0, uint32_t c1,
                                       uint32_t &o0, uint32_t &o1) {
    uint32_t ks2 = k0 ^ k1 ^ 0x1BD11BDAu;
    uint32_t x0 = c0 + k0;
    uint32_t x1 = c1 + k1;
#define TFR(r) { x0 += x1; x1 = __funnelshift_l(x1, x1, (r)); x1 ^= x0; }
    TFR(13) TFR(15) TFR(26) TFR(6)
    x0 += k1;  x1 += ks2 + 1u;
    TFR(17) TFR(29) TFR(16) TFR(24)
    x0 += ks2; x1 += k0 + 2u;
    TFR(13) TFR(15) TFR(26) TFR(6)
    x0 += k0;  x1 += k1 + 3u;
    TFR(17) TFR(29) TFR(16) TFR(24)
    x0 += k1;  x1 += ks2 + 4u;
    TFR(13) TFR(15) TFR(26) TFR(6)
    x0 += ks2; x1 += k0 + 5u;
#undef TFR
    o0 = x0; o1 = x1;
}

__device__ __forceinline__ K2 keyderive(K2 k, uint32_t hi, uint32_t lo) {
    K2 r; tf2x32(k.a, k.b, hi, lo, r.a, r.b); return r;
}
__device__ __forceinline__ uint32_t bits32(K2 k, uint32_t hi, uint32_t lo) {
    uint32_t a, b; tf2x32(k.a, k.b, hi, lo, a, b); return a ^ b;
}
__device__ __forceinline__ float u01_from_bits(uint32_t bits) {
    return SUBR(__uint_as_float((bits >> 9) | 0x3f800000u), 1.0f);   // [0,1)
}
__device__ __forceinline__ float uniform01(K2 k) { return u01_from_bits(bits32(k, 0u, 0u)); }

// XLA ErfInv f32 (Giles), un-contracted
__device__ __forceinline__ float erfinv_xla(float x) {
    float w = -log1pf(-MULR(x, x));
    float p;
    if (w < 5.0f) {
        w = SUBR(w, 2.5f);
        p = 2.81022636e-08f;
        p = ADDR(MULR(p, w), 3.43273939e-07f);
        p = ADDR(MULR(p, w), -3.5233877e-06f);
        p = ADDR(MULR(p, w), -4.39150654e-06f);
        p = ADDR(MULR(p, w), 0.00021858087f);
        p = ADDR(MULR(p, w), -0.00125372503f);
        p = ADDR(MULR(p, w), -0.00417768164f);
        p = ADDR(MULR(p, w), 0.246640727f);
        p = ADDR(MULR(p, w), 1.50140941f);
    } else {
        w = SUBR(sqrtf(w), 3.0f);
        p = -0.000200214257f;
        p = ADDR(MULR(p, w), 0.000100950558f);
        p = ADDR(MULR(p, w), 0.00134934322f);
        p = ADDR(MULR(p, w), -0.00367342844f);
        p = ADDR(MULR(p, w), 0.00573950773f);
        p = ADDR(MULR(p, w), -0.0076224613f);
        p = ADDR(MULR(p, w), 0.00943887047f);
        p = ADDR(MULR(p, w), 1.00167406f);
        p = ADDR(MULR(p, w), 2.83297682f);
    }
    return MULR(p, x);
}

__device__ __forceinline__ float normal_from_bits(uint32_t bits) {
    const float LO = -0.99999994f;
    float f = u01_from_bits(bits);
    float val = fmaxf(LO, ADDR(MULR(f, 2.0f), LO));
    return MULR(1.41421356237309515f, erfinv_xla(val));
}
__device__ __forceinline__ float normal_scalar(K2 k) { return normal_from_bits(bits32(k, 0u, 0u)); }

// jax._src.random._gamma_one, log_space=True, alpha=63.5
__device__ float loggamma_a635(K2 key_elem) {
    const float d = SUBR(63.5f, 0.33333334f);
    const float c = DIVR(0.33333334f, sqrtf(d));
    K2 key = keyderive(key_elem, 0u, 0u);
    float V = 1.0f;
    for (int it = 0; it < 64; ++it) {
        K2 nkey = keyderive(key, 0u, 0u);
        K2 xkey = keyderive(key, 0u, 1u);
        K2 Ukey = keyderive(key, 0u, 2u);
        key = nkey;
        float x = 0.0f, v = -1.0f;
        for (int j = 0; j < 8; ++j) {
            K2 sub = keyderive(xkey, 0u, 1u);
            x = normal_scalar(sub);
            v = ADDR(1.0f, MULR(x, c));
            if (v > 0.0f) break;
            xkey = keyderive(xkey, 0u, 0u);
        }
        float X = MULR(x, x);
        V = MULR(MULR(v, v), v);
        float U = uniform01(Ukey);
        if (U < SUBR(1.0f, MULR(0.0331f, MULR(X, X)))) break;
        if (logf(U) < ADDR(MULR(X, 0.5f), MULR(d, ADDR(SUBR(1.0f, V), logf(V))))) break;
    }
    return ADDR(logf(d), logf(V));
}

__device__ __forceinline__ float beta_e(K2 kA, K2 kB) {
    float la = loggamma_a635(kA);
    float lb = loggamma_a635(kB);
    float mx = fmaxf(la, lb);
    float ea = expf(SUBR(la, mx));
    float eb = expf(SUBR(lb, mx));
    return DIVR(ea, ADDR(ea, eb));
}

// ---------------- kernel 1: h = x@W_enc + b_enc, fused mu + kappa epilogue ----------------
__global__ __launch_bounds__(256, 2) void enc_kernel(const float* __restrict__ X,
                                                     const float* __restrict__ W,
                                                     const float* __restrict__ bias,
                                                     const float* __restrict__ Wvar,
                                                     const float* __restrict__ bvar) {
    __shared__ float As[2][16][128];
    __shared__ float Bs[2][16][128];
    int tid = threadIdx.x;
    int tx  = tid & 15;
    int ty  = tid >> 4;
    int rowBase = blockIdx.x * 128;

    unsigned long long acc2[8][4];
#pragma unroll
    for (int i = 0; i < 8; i++)
#pragma unroll
        for (int j = 0; j < 4; j++) acc2[i][j] = 0ull;

    // stage 0 load
#pragma unroll
    for (int l = 0; l < 2; l++) {
        int idx = tid + l * 256;
        int r = idx >> 2, f = idx & 3;
        float4 v = *(const float4*)&X[(rowBase + r) * D_IN + f * 4];
        As[0][f * 4 + 0][r] = v.x; As[0][f * 4 + 1][r] = v.y;
        As[0][f * 4 + 2][r] = v.z; As[0][f * 4 + 3][r] = v.w;
    }
#pragma unroll
    for (int l = 0; l < 2; l++) {
        int idx = tid + l * 256;
        int kk = idx >> 5, c4 = idx & 31;
        *(float4*)&Bs[0][kk][c4 * 4] = *(const float4*)&W[(kk) * DIMZ + c4 * 4];
    }
    __syncthreads();

    const int NIT = D_IN / 16;   // 49
    for (int t = 0; t < NIT; ++t) {
        int cur = t & 1, nxt = cur ^ 1;
        if (t + 1 < NIT) {
            int k0 = (t + 1) * 16;
#pragma unroll
            for (int l = 0; l < 2; l++) {
                int idx = tid + l * 256;
                int r = idx >> 2, f = idx & 3;
                float4 v = *(const float4*)&X[(rowBase + r) * D_IN + k0 + f * 4];
                As[nxt][f * 4 + 0][r] = v.x; As[nxt][f * 4 + 1][r] = v.y;
                As[nxt][f * 4 + 2][r] = v.z; As[nxt][f * 4 + 3][r] = v.w;
            }
#pragma unroll
            for (int l = 0; l < 2; l++) {
                int idx = tid + l * 256;
                int kk = idx >> 5, c4 = idx & 31;
                *(float4*)&Bs[nxt][kk][c4 * 4] = *(const float4*)&W[(k0 + kk) * DIMZ + c4 * 4];
            }
        }
#pragma unroll
        for (int kk = 0; kk < 16; ++kk) {
            float4 a0 = *(const float4*)&As[cur][kk][ty * 8];
            float4 a1 = *(const float4*)&As[cur][kk][ty * 8 + 4];
            float4 b0 = *(const float4*)&Bs[cur][kk][tx * 8];
            float4 b1 = *(const float4*)&Bs[cur][kk][tx * 8 + 4];
            unsigned long long bp[4] = {packf2(b0.x, b0.y), packf2(b0.z, b0.w),
                                        packf2(b1.x, b1.y), packf2(b1.z, b1.w)};
            float av[8] = {a0.x, a0.y, a0.z, a0.w, a1.x, a1.y, a1.z, a1.w};
#pragma unroll
            for (int i = 0; i < 8; i++) {
                unsigned long long ai = packf2(av[i], av[i]);
                fma2(acc2[i][0], ai, bp[0]);
                fma2(acc2[i][1], ai, bp[1]);
                fma2(acc2[i][2], ai, bp[2]);
                fma2(acc2[i][3], ai, bp[3]);
            }
        }
        __syncthreads();
    }

    // epilogue: bias, row norm (mu), kappa
    float bcol[8], wvr[8];
#pragma unroll
    for (int j = 0; j < 8; j++) { bcol[j] = bias[tx * 8 + j]; wvr[j] = Wvar[tx * 8 + j]; }
    float bv = bvar[0];

#pragma unroll
    for (int i = 0; i < 8; i++) {
        float h[8];
        unpackf2(acc2[i][0], h[0], h[1]);
        unpackf2(acc2[i][1], h[2], h[3]);
        unpackf2(acc2[i][2], h[4], h[5]);
        unpackf2(acc2[i][3], h[6], h[7]);
        float nrm = 0.0f, kp = 0.0f;
#pragma unroll
        for (int j = 0; j < 8; j++) {
            h[j] += bcol[j];
            nrm = fmaf(h[j], h[j], nrm);
            kp  = fmaf(h[j], wvr[j], kp);
        }
#pragma unroll
        for (int o = 8; o > 0; o >>= 1) {
            nrm += __shfl_xor_sync(0xffffffffu, nrm, o);
            kp  += __shfl_xor_sync(0xffffffffu, kp, o);
        }
        int row = rowBase + ty * 8 + i;
        float rinv = 1.0f / (sqrtf(nrm) + 1e-8f);
        float4 m0 = {h[0] * rinv, h[1] * rinv, h[2] * rinv, h[3] * rinv};
        float4 m1 = {h[4] * rinv, h[5] * rinv, h[6] * rinv, h[7] * rinv};
        *(float4*)&g_h[row * DIMZ + tx * 8]     = m0;
        *(float4*)&g_h[row * DIMZ + tx * 8 + 4] = m1;
        if (tx == 0) {
            float xv = kp + bv;
            float sp = fmaxf(xv, 0.0f) + log1pf(expf(-fabsf(xv)));
            g_kappa[row] = sp + 1.0f;
        }
    }
}

// ---------------- kernel 2: lazy vMF rejection sampler (thread per row) ----------------
__global__ __launch_bounds__(256) void sampler_kernel() {
    int row = blockIdx.x * blockDim.x + threadIdx.x;
    if (row >= B_ROWS) return;

    K2 root; root.a = 0u; root.b = 42u;        // jax.random.key(42)
    K2 ke   = keyderive(root, 0u, 0u);         // ke, ku, kv = split(key, 3)
    K2 ku   = keyderive(root, 0u, 1u);
    K2 keyA = keyderive(ke, 0u, 0u);           // beta: key_a, key_b = split(ke)
    K2 keyB = keyderive(ke, 0u, 1u);

    float kap = g_kappa[row];
    float c  = sqrtf(ADDR(MULR(4.0f, MULR(kap, kap)), 16129.0f));
    float bt = DIVR(ADDR(MULR(-2.0f, kap), c), 127.0f);
    float ba = DIVR(127.0f, MULR(4.0f, kap));
    float s  = fminf(fmaxf(SUBR(kap, 10.0f), 0.0f), 1.0f);
    float bb = ADDR(MULR(ba, s), MULR(bt, SUBR(1.0f, s)));
    float aa = DIVR(ADDR(ADDR(127.0f, MULR(2.0f, kap)), c), 4.0f);
    float dd = SUBR(DIVR(MULR(MULR(4.0f, aa), bb), ADDR(1.0f, bb)),
                    MULR(127.0f, (float)4.844187086458591));

    float wsel = 0.0f;
    for (uint32_t k = 0; k < KPROP; k++) {
        uint32_t i = (uint32_t)row * 64u + k;
        float e = beta_e(keyderive(keyA, 0u, i), keyderive(keyB, 0u, i));
        float denom = SUBR(1.0f, MULR(SUBR(1.0f, bb), e));
        wsel = DIVR(SUBR(1.0f, MULR(ADDR(1.0f, bb), e)), denom);
        float t = DIVR(MULR(MULR(2.0f, aa), bb), denom);
        float uf = fmaxf(1e-20f, ADDR(u01_from_bits(bits32(ku, 0u, i)), 1e-20f));
        float lhs = ADDR(SUBR(MULR(127.0f, logf(t)), t), dd);
        if (lhs > logf(uf)) break;
    }
    g_w[row] = wsel;
}

// ---------------- kernel 3: warp-per-row tangent + Householder + decoder ----------------
__device__ __forceinline__ float warpAllSum(float v) {
#pragma unroll
    for (int o = 16; o > 0; o >>= 1) v += __shfl_xor_sync(0xffffffffu, v, o);
    return v;
}

__global__ __launch_bounds__(256) void finish_kernel(const float* __restrict__ Wdec,
                                                     const float* __restrict__ bdec,
                                                     float* __restrict__ out) {
    __shared__ float wd[DIMZ * NCLS];
    int tid = threadIdx.x;
    for (int i = tid; i < DIMZ * NCLS; i += 256) wd[i] = Wdec[i];
    __syncthreads();

    int lane = tid & 31;
    int row = blockIdx.x * 8 + (tid >> 5);

    // this lane owns columns j = lane*4 + q; g_h already holds mu
    float4 mv = *(const float4*)&g_h[row * DIMZ + lane * 4];
    float mu[4] = {mv.x, mv.y, mv.z, mv.w};

    K2 root; root.a = 0u; root.b = 42u;
    K2 kv = keyderive(root, 0u, 2u);

    float v[4];
    float vs = 0.0f;
#pragma unroll
    for (int q = 0; q < 4; q++) {
        int j = lane * 4 + q;
        v[q] = 0.0f;
        if (j >= 1)
            v[q] = normal_from_bits(bits32(kv, 0u, (uint32_t)row * 127u + (uint32_t)(j - 1)));
        vs = fmaf(v[q], v[q], vs);
    }
    vs = warpAllSum(vs);
    float vninv = 1.0f / sqrtf(vs);

    float w = g_w[row];
    float wperp = sqrtf(fmaxf(1.0f - w * w, 1e-10f));

    float x[4], uh[4];
    float un = 0.0f;
#pragma unroll
    for (int q = 0; q < 4; q++) {
        int j = lane * 4 + q;
        x[q]  = (j == 0) ? w : wperp * (v[q] * vninv);
        uh[q] = ((j == 0) ? 1.0f : 0.0f) - mu[q];
        un = fmaf(uh[q], uh[q], un);
    }
    un = warpAllSum(un);
    float uinv = 1.0f / (sqrtf(un) + 1e-5f);

    float xd = 0.0f;
#pragma unroll
    for (int q = 0; q < 4; q++) { uh[q] *= uinv; xd = fmaf(x[q], uh[q], xd); }
    xd = warpAllSum(xd);

    float z[4];
#pragma unroll
    for (int q = 0; q < 4; q++) z[q] = x[q] - 2.0f * xd * uh[q];

    // decoder: out[row, c] = sum_r z_r * Wdec[r, c] + bdec[c]
    float acc[NCLS];
#pragma unroll
    for (int c = 0; c < NCLS; c++) acc[c] = 0.0f;
#pragma unroll
    for (int q = 0; q < 4; q++) {
        int r = lane * 4 + q;
#pragma unroll
        for (int c = 0; c < NCLS; c++) acc[c] = fmaf(z[q], wd[r * NCLS + c], acc[c]);
    }
#pragma unroll
    for (int c = 0; c < NCLS; c++) {
        acc[c] = warpAllSum(acc[c]);
        if (lane == c) out[row * NCLS + c] = acc[c] + bdec[c];
    }
}

extern "C" void kernel_launch(void* const* d_in, const int* in_sizes, int n_in,
                              void* d_out, int out_size) {
    const float* x    = (const float*)d_in[0];
    const float* Wenc = (const float*)d_in[1];
    const float* benc = (const float*)d_in[2];
    const float* Wvar = (const float*)d_in[3];
    const float* bvar = (const float*)d_in[4];
    const float* Wdec = (const float*)d_in[5];
    const float* bdec = (const float*)d_in[6];
    float* out = (float*)d_out;

    enc_kernel<<<B_ROWS / 128, 256>>>(x, Wenc, benc, Wvar, bvar);
    sampler_kernel<<<B_ROWS / 256, 256>>>();
    finish_kernel<<<B_ROWS / 8, 256>>>(Wdec, bdec, out);
}